// round 1
// baseline (speedup 1.0000x reference)
#include <cuda_runtime.h>
#include <cstdint>

// Scratch for Q/K/V projections: [2048, 1024] each (row i, col h*64+d)
__device__ float g_Q[2048 * 1024];
__device__ float g_K[2048 * 1024];
__device__ float g_V[2048 * 1024];

// ---------------------------------------------------------------------------
// Kernel 1: QKV projection GEMM.  C = X @ W + b for W in {Wq,Wk,Wv} (z-dim).
// Tile: 128x64, BK=16, 256 threads (16x16), 8x4 per-thread micro-tile.
// ---------------------------------------------------------------------------
__global__ __launch_bounds__(256, 4)
void qkv_gemm_kernel(const float* __restrict__ X,
                     const float* __restrict__ Wq, const float* __restrict__ bq,
                     const float* __restrict__ Wk, const float* __restrict__ bk,
                     const float* __restrict__ Wv, const float* __restrict__ bv)
{
    __shared__ float As[16][128];   // [k][m]  (X tile, transposed)
    __shared__ float Bs[16][64];    // [k][n]  (W tile)

    const float* W; const float* bias; float* C;
    if (blockIdx.z == 0)      { W = Wq; bias = bq; C = g_Q; }
    else if (blockIdx.z == 1) { W = Wk; bias = bk; C = g_K; }
    else                      { W = Wv; bias = bv; C = g_V; }

    const int tid = threadIdx.x;
    const int tx = tid & 15, ty = tid >> 4;
    const int m0 = blockIdx.y * 128, n0 = blockIdx.x * 64;

    float acc[8][4];
#pragma unroll
    for (int r = 0; r < 8; ++r)
#pragma unroll
        for (int c = 0; c < 4; ++c) acc[r][c] = 0.f;

    for (int k0 = 0; k0 < 1024; k0 += 16) {
        // Load X tile 128x16 (2 float4 per thread), store transposed
#pragma unroll
        for (int l = tid; l < 512; l += 256) {
            int row = l >> 2, kk = (l & 3) << 2;
            float4 v = *(const float4*)(X + (size_t)(m0 + row) * 1024 + k0 + kk);
            As[kk + 0][row] = v.x; As[kk + 1][row] = v.y;
            As[kk + 2][row] = v.z; As[kk + 3][row] = v.w;
        }
        // Load W tile 16x64 (1 float4 per thread)
        {
            int row = tid >> 4, c4 = (tid & 15) << 2;
            *(float4*)&Bs[row][c4] =
                *(const float4*)(W + (size_t)(k0 + row) * 1024 + n0 + c4);
        }
        __syncthreads();

#pragma unroll
        for (int k = 0; k < 16; ++k) {
            float4 b  = *(float4*)&Bs[k][tx << 2];
            float4 a0 = *(float4*)&As[k][ty << 3];
            float4 a1 = *(float4*)&As[k][(ty << 3) + 4];
            float ar[8] = {a0.x, a0.y, a0.z, a0.w, a1.x, a1.y, a1.z, a1.w};
#pragma unroll
            for (int r = 0; r < 8; ++r) {
                acc[r][0] += ar[r] * b.x;
                acc[r][1] += ar[r] * b.y;
                acc[r][2] += ar[r] * b.z;
                acc[r][3] += ar[r] * b.w;
            }
        }
        __syncthreads();
    }

    float4 bb = *(const float4*)(bias + n0 + (tx << 2));
#pragma unroll
    for (int r = 0; r < 8; ++r) {
        int row = m0 + (ty << 3) + r;
        float4 o;
        o.x = acc[r][0] + bb.x; o.y = acc[r][1] + bb.y;
        o.z = acc[r][2] + bb.z; o.w = acc[r][3] + bb.w;
        *(float4*)(C + (size_t)row * 1024 + n0 + (tx << 2)) = o;
    }
}

// ---------------------------------------------------------------------------
// Kernel 2: flash-style attention per (query-tile 64, head).
//   - a_k = Q_tile @ W_rel_k computed once per block (bias term, pre-scale)
//   - online softmax (64x64 key tiles), mask applied as (1-m)*FLT_MIN
//   - rel_v band folded into PV accumulation for the 3 diagonal tiles
// Dynamic smem = 103424 bytes.
// ---------------------------------------------------------------------------
#define ATTN_SMEM_FLOATS 25856  /* 4352+4352+8448+8448+64+192 */

__global__ __launch_bounds__(256, 2)
void attn_kernel(const float* __restrict__ mask,
                 const float* __restrict__ Wrk,   // [64][129]
                 const float* __restrict__ Wrv,   // [129][64]
                 float* __restrict__ out)
{
    extern __shared__ float sm[];
    float* Qs   = sm;            // [64][68]
    float* Ps   = sm + 4352;     // [64][68]
    float* ak   = sm + 8704;     // [64][132]
    float* KVu  = sm + 17152;    // union: Wrk staging [64][132] OR Kts[64][64]+Vs[64][64]
    float* ms   = sm + 25600;    // [64]
    float* mrow = sm + 25664;    // [64]
    float* lrow = sm + 25728;    // [64]
    float* frow = sm + 25792;    // [64]

    const int tid = threadIdx.x;
    const int tx = tid & 15, ty = tid >> 4;
    const int h  = blockIdx.y;
    const int i0 = blockIdx.x * 64;
    const int hc = h * 64;

    // ---- Load Q tile (rows i0..i0+63, cols h*64..h*64+63) ----
#pragma unroll
    for (int l = tid; l < 1024; l += 256) {
        int row = l >> 4, c4 = (l & 15) << 2;
        float4 v = *(const float4*)(g_Q + (size_t)(i0 + row) * 1024 + hc + c4);
        *(float4*)(Qs + row * 68 + c4) = v;
    }
    // ---- Stage W_rel_k [64][129] into KVu [64][132], zero pad cols 129..131 ----
    for (int l = tid; l < 64 * 129; l += 256) {
        int d = l / 129, w = l - d * 129;
        KVu[d * 132 + w] = Wrk[l];
    }
    if (tid < 192) { int d = tid / 3, c = 129 + (tid % 3); KVu[d * 132 + c] = 0.f; }
    if (tid < 64)  { mrow[tid] = -1e30f; lrow[tid] = 0.f; }
    __syncthreads();

    // ---- a_k[i][w] = sum_d Qs[i][d] * Wrk[d][w]  (4 w's per thread) ----
    for (int idx = tid; idx < 64 * 33; idx += 256) {
        int i = idx / 33, w4 = idx - i * 33;
        int w = w4 << 2;
        float s0 = 0.f, s1 = 0.f, s2 = 0.f, s3 = 0.f;
        const float* qrow = Qs + i * 68;
#pragma unroll 8
        for (int d = 0; d < 64; ++d) {
            float a = qrow[d];
            float4 bw = *(const float4*)(KVu + d * 132 + w);
            s0 += a * bw.x; s1 += a * bw.y; s2 += a * bw.z; s3 += a * bw.w;
        }
        if (w < 128) {
            float4 o; o.x = s0; o.y = s1; o.z = s2; o.w = s3;
            *(float4*)(ak + i * 132 + w) = o;
        } else {
            ak[i * 132 + 128] = s0;
        }
    }
    __syncthreads();

    float* Kts = KVu;            // [d][j] = [64][64]
    float* Vs  = KVu + 4096;     // [j][d] = [64][64]

    float acc[4][4];
#pragma unroll
    for (int r = 0; r < 4; ++r)
#pragma unroll
        for (int c = 0; c < 4; ++c) acc[r][c] = 0.f;

    for (int jt = 0; jt < 32; ++jt) {
        const int j0 = jt * 64;
        // ---- load K tile transposed [d][j] + V tile [j][d] + mask slice ----
#pragma unroll
        for (int l = tid; l < 1024; l += 256) {
            int j = l >> 4, d4 = (l & 15) << 2;
            float4 v = *(const float4*)(g_K + (size_t)(j0 + j) * 1024 + hc + d4);
            Kts[(d4 + 0) * 64 + j] = v.x; Kts[(d4 + 1) * 64 + j] = v.y;
            Kts[(d4 + 2) * 64 + j] = v.z; Kts[(d4 + 3) * 64 + j] = v.w;
        }
#pragma unroll
        for (int l = tid; l < 1024; l += 256) {
            int j = l >> 4, d4 = (l & 15) << 2;
            *(float4*)(Vs + j * 64 + d4) =
                *(const float4*)(g_V + (size_t)(j0 + j) * 1024 + hc + d4);
        }
        if (tid < 64) ms[tid] = mask[j0 + tid];
        __syncthreads();

        // ---- S = Q @ K^T  (each thread: 4x4) ----
        float sa[4][4];
#pragma unroll
        for (int r = 0; r < 4; ++r)
#pragma unroll
            for (int c = 0; c < 4; ++c) sa[r][c] = 0.f;

#pragma unroll 8
        for (int d = 0; d < 64; ++d) {
            float4 b = *(float4*)(Kts + d * 64 + (tx << 2));
            float a0 = Qs[(ty * 4 + 0) * 68 + d];
            float a1 = Qs[(ty * 4 + 1) * 68 + d];
            float a2 = Qs[(ty * 4 + 2) * 68 + d];
            float a3 = Qs[(ty * 4 + 3) * 68 + d];
            sa[0][0] += a0 * b.x; sa[0][1] += a0 * b.y; sa[0][2] += a0 * b.z; sa[0][3] += a0 * b.w;
            sa[1][0] += a1 * b.x; sa[1][1] += a1 * b.y; sa[1][2] += a1 * b.z; sa[1][3] += a1 * b.w;
            sa[2][0] += a2 * b.x; sa[2][1] += a2 * b.y; sa[2][2] += a2 * b.z; sa[2][3] += a2 * b.w;
            sa[3][0] += a3 * b.x; sa[3][1] += a3 * b.y; sa[3][2] += a3 * b.z; sa[3][3] += a3 * b.w;
        }

        // ---- bias (pre-scale) + scale + mask → Ps ----
        const int delta = j0 - i0 + 64;
#pragma unroll
        for (int r = 0; r < 4; ++r) {
            int il = ty * 4 + r;
#pragma unroll
            for (int c = 0; c < 4; ++c) {
                int jl = tx * 4 + c;
                float s = sa[r][c];
                int slot = delta + jl - il;
                if (slot >= 0 && slot <= 128) s += ak[il * 132 + slot];
                s = s * 0.125f + (1.0f - ms[jl]) * (-3.4028235e38f);
                Ps[il * 68 + jl] = s;
            }
        }
        __syncthreads();

        // ---- online softmax update: 4 threads per row ----
        {
            int row = tid >> 2, l4 = tid & 3;
            float* pr = Ps + row * 68;
            float mx = -1e30f;
            for (int c = l4; c < 64; c += 4) mx = fmaxf(mx, pr[c]);
            mx = fmaxf(mx, __shfl_xor_sync(0xffffffffu, mx, 1));
            mx = fmaxf(mx, __shfl_xor_sync(0xffffffffu, mx, 2));
            float m_old = mrow[row];
            float m_new = fmaxf(m_old, mx);
            float sum = 0.f;
            for (int c = l4; c < 64; c += 4) {
                float p = __expf(pr[c] - m_new);
                pr[c] = p;
                sum += p;
            }
            sum += __shfl_xor_sync(0xffffffffu, sum, 1);
            sum += __shfl_xor_sync(0xffffffffu, sum, 2);
            if (l4 == 0) {
                float f = __expf(m_old - m_new);
                frow[row] = f;
                lrow[row] = lrow[row] * f + sum;
                mrow[row] = m_new;
            }
        }
        __syncthreads();

        // ---- rescale accumulators ----
        float fr[4];
#pragma unroll
        for (int r = 0; r < 4; ++r) fr[r] = frow[ty * 4 + r];
#pragma unroll
        for (int r = 0; r < 4; ++r)
#pragma unroll
            for (int c = 0; c < 4; ++c) acc[r][c] *= fr[r];

        // ---- PV accumulation (+ folded rel_v band for diagonal tiles) ----
        const bool band = (delta >= 0 && delta <= 128);
#pragma unroll 4
        for (int j = 0; j < 64; ++j) {
            float p[4];
            p[0] = Ps[(ty * 4 + 0) * 68 + j];
            p[1] = Ps[(ty * 4 + 1) * 68 + j];
            p[2] = Ps[(ty * 4 + 2) * 68 + j];
            p[3] = Ps[(ty * 4 + 3) * 68 + j];
            float4 v = *(float4*)(Vs + j * 64 + (tx << 2));
#pragma unroll
            for (int r = 0; r < 4; ++r) {
                acc[r][0] += p[r] * v.x; acc[r][1] += p[r] * v.y;
                acc[r][2] += p[r] * v.z; acc[r][3] += p[r] * v.w;
            }
            if (band) {
#pragma unroll
                for (int r = 0; r < 4; ++r) {
                    int w = delta + j - (ty * 4 + r);
                    if (w >= 0 && w <= 128) {
                        float4 wv = *(const float4*)(Wrv + w * 64 + (tx << 2));
                        acc[r][0] += p[r] * wv.x; acc[r][1] += p[r] * wv.y;
                        acc[r][2] += p[r] * wv.z; acc[r][3] += p[r] * wv.w;
                    }
                }
            }
        }
        __syncthreads();
    }

    // ---- epilogue: normalize by l, write out[n][h*64+d] ----
#pragma unroll
    for (int r = 0; r < 4; ++r) {
        int row = ty * 4 + r;
        float inv = 1.0f / lrow[row];
        float4 o;
        o.x = acc[r][0] * inv; o.y = acc[r][1] * inv;
        o.z = acc[r][2] * inv; o.w = acc[r][3] * inv;
        *(float4*)(out + (size_t)(i0 + row) * 1024 + hc + (tx << 2)) = o;
    }
}

// ---------------------------------------------------------------------------
extern "C" void kernel_launch(void* const* d_in, const int* in_sizes, int n_in,
                              void* d_out, int out_size)
{
    const float* X   = (const float*)d_in[0];
    const float* msk = (const float*)d_in[1];
    const float* Wq  = (const float*)d_in[2];
    const float* bq  = (const float*)d_in[3];
    const float* Wk  = (const float*)d_in[4];
    const float* bk  = (const float*)d_in[5];
    const float* Wv  = (const float*)d_in[6];
    const float* bv  = (const float*)d_in[7];
    const float* Wrk = (const float*)d_in[8];
    const float* Wrv = (const float*)d_in[9];
    float* out = (float*)d_out;

    cudaFuncSetAttribute(attn_kernel,
                         cudaFuncAttributeMaxDynamicSharedMemorySize,
                         ATTN_SMEM_FLOATS * 4);

    dim3 gGemm(16, 16, 3);   // 1024/64 n-tiles, 2048/128 m-tiles, {Q,K,V}
    qkv_gemm_kernel<<<gGemm, 256>>>(X, Wq, bq, Wk, bk, Wv, bv);

    dim3 gAttn(32, 16);      // 2048/64 query tiles, 16 heads
    attn_kernel<<<gAttn, 256, ATTN_SMEM_FLOATS * 4>>>(msk, Wrk, Wrv, out);
}